// round 7
// baseline (speedup 1.0000x reference)
#include <cuda_runtime.h>

// CAM_Module channel attention. B=16, C=512, C1=256, HW=4096
//   q      = W[256,512] @ x_b[512,4096] + bias            (GEMM1, NN)
//   energy = q[256,4096] @ x_b[512,4096]^T / 64           (GEMM2, NT)
//   attn   = softmax(energy, last dim 512)
//   out    = gamma * (attn[256,512] @ x_b[512,4096]) + q  (GEMM3, NN)
// All GEMMs 3xTF32 (Dekker split, fp32-grade). Split precomputed at smem-store
// time as packed {hi,lo} uint2; XOR-swizzled smem (no padding, 48KB static).

static constexpr int NB  = 16;
static constexpr int NC  = 512;
static constexpr int NC1 = 256;
static constexpr int NHW = 4096;

__device__ float g_q[(size_t)NB * NC1 * NHW];    // 64 MB scratch
__device__ float g_attn[(size_t)NB * NC1 * NC];  //  8 MB scratch

__device__ __forceinline__ unsigned f2tf(float f) {
    unsigned u;
    asm("cvt.rna.tf32.f32 %0, %1;" : "=r"(u) : "f"(f));
    return u;
}

// Dekker split: v ~= hi + lo, both exactly representable in tf32.
__device__ __forceinline__ uint2 split_tf32(float v) {
    const unsigned hi = f2tf(v);
    const unsigned lo = f2tf(v - __uint_as_float(hi));
    return make_uint2(hi, lo);
}

// XOR swizzle on the m index: flips bits 2..3 by ((k&3) ^ (k>>2)).
// Conflict-free STS.64/LDS.64 for A-stores, NT B-stores, all fragment reads.
__device__ __forceinline__ int swz(int k, int m) {
    return m ^ ((((k & 3) ^ (k >> 2))) << 2);
}

__device__ __forceinline__ void mma_tf32(float* c, const unsigned* a, const unsigned* b) {
    asm volatile(
        "mma.sync.aligned.m16n8k8.row.col.f32.tf32.tf32.f32 "
        "{%0,%1,%2,%3}, {%4,%5,%6,%7}, {%8,%9}, {%0,%1,%2,%3};"
        : "+f"(c[0]), "+f"(c[1]), "+f"(c[2]), "+f"(c[3])
        : "r"(a[0]), "r"(a[1]), "r"(a[2]), "r"(a[3]),
          "r"(b[0]), "r"(b[1]));
}

// ---------------------------------------------------------------------------
// Tensor-core GEMM: BM=128 x BN=64 x BK=16, 256 threads (8 warps, 4x2),
// warp tile 32x32 = 2x4 m16n8k8, 3xTF32. Double-buffered packed-uint2 smem.
// MODE 0: NN, A batch-shared (conv_w), C = A@B + bias[m]
// MODE 1: NN, A per-batch (attn),      C = gamma*(A@B) + res
// MODE 2: NT, A per-batch (q), B=[N,K] row-major, C = scale*(A@B^T)
// grid (N/64, M/128, batch)
// ---------------------------------------------------------------------------
template <int MODE>
__global__ __launch_bounds__(256, 2)
void mma_gemm_kernel(const float* __restrict__ A_, const float* __restrict__ x,
                     const float* __restrict__ bias, const float* __restrict__ gamma,
                     const float* __restrict__ res, float* __restrict__ Cout,
                     int M, int N, int K, float scale)
{
    const int b = blockIdx.z;
    const float* A = (MODE == 0) ? A_ : A_ + (size_t)b * M * K;
    const float* B = (MODE == 2) ? x + (size_t)b * N * K : x + (size_t)b * K * N;
    float*      Cp = Cout + (size_t)b * M * N;

    __shared__ __align__(16) uint2 As2[2][16][128];  // 32768 B
    __shared__ __align__(16) uint2 Bs2[2][16][64];   // 16384 B  (total = 48 KB)

    const int t    = threadIdx.x;
    const int lane = t & 31;
    const int warp = t >> 5;
    const int wm   = (warp & 3) * 32;
    const int wn   = (warp >> 2) * 32;
    const int g    = lane >> 2;         // 0..7
    const int tq   = lane & 3;          // 0..3

    const int m0 = blockIdx.y * 128;
    const int n0 = blockIdx.x * 64;

    // A tile loads (128x16): 2 float4/thread along K, split+transpose-store
    const int am0 = t >> 2;             // 0..63
    const int am1 = am0 + 64;           // 64..127
    const int ak  = (t & 3) << 2;       // 0,4,8,12
    // B tile NN (16x64): 1 float4/thread along N
    const int bk = t >> 4;              // 0..15
    const int bn = (t & 15) << 2;       // 0..60
    // B tile NT (64 x 16): 1 float4/thread along K, split+transpose-store
    const int cn = t >> 2;              // 0..63
    const int ck = (t & 3) << 2;        // 0,4,8,12

    float acc[2][4][4];
#pragma unroll
    for (int mi = 0; mi < 2; mi++)
#pragma unroll
        for (int ni = 0; ni < 4; ni++)
#pragma unroll
            for (int r = 0; r < 4; r++) acc[mi][ni][r] = 0.0f;

    const int nT = K >> 4;

    // ---- prefetch tile 0 ----
    float4 pa0 = *(const float4*)&A[(size_t)(m0 + am0) * K + ak];
    float4 pa1 = *(const float4*)&A[(size_t)(m0 + am1) * K + ak];
    float4 pb;
    if (MODE == 2) pb = *(const float4*)&B[(size_t)(n0 + cn) * K + ck];
    else           pb = *(const float4*)&B[(size_t)bk * N + n0 + bn];

    {
        As2[0][ak + 0][swz(ak + 0, am0)] = split_tf32(pa0.x);
        As2[0][ak + 1][swz(ak + 1, am0)] = split_tf32(pa0.y);
        As2[0][ak + 2][swz(ak + 2, am0)] = split_tf32(pa0.z);
        As2[0][ak + 3][swz(ak + 3, am0)] = split_tf32(pa0.w);
        As2[0][ak + 0][swz(ak + 0, am1)] = split_tf32(pa1.x);
        As2[0][ak + 1][swz(ak + 1, am1)] = split_tf32(pa1.y);
        As2[0][ak + 2][swz(ak + 2, am1)] = split_tf32(pa1.z);
        As2[0][ak + 3][swz(ak + 3, am1)] = split_tf32(pa1.w);
        if (MODE == 2) {
            Bs2[0][ck + 0][swz(ck + 0, cn)] = split_tf32(pb.x);
            Bs2[0][ck + 1][swz(ck + 1, cn)] = split_tf32(pb.y);
            Bs2[0][ck + 2][swz(ck + 2, cn)] = split_tf32(pb.z);
            Bs2[0][ck + 3][swz(ck + 3, cn)] = split_tf32(pb.w);
        } else {
            Bs2[0][bk][swz(bk, bn + 0)] = split_tf32(pb.x);
            Bs2[0][bk][swz(bk, bn + 1)] = split_tf32(pb.y);
            Bs2[0][bk][swz(bk, bn + 2)] = split_tf32(pb.z);
            Bs2[0][bk][swz(bk, bn + 3)] = split_tf32(pb.w);
        }
    }
    __syncthreads();

    for (int kt = 0; kt < nT; kt++) {
        const int  cur      = kt & 1;
        const bool has_next = (kt + 1 < nT);
        if (has_next) {
            const int k0 = (kt + 1) << 4;
            pa0 = *(const float4*)&A[(size_t)(m0 + am0) * K + k0 + ak];
            pa1 = *(const float4*)&A[(size_t)(m0 + am1) * K + k0 + ak];
            if (MODE == 2) pb = *(const float4*)&B[(size_t)(n0 + cn) * K + k0 + ck];
            else           pb = *(const float4*)&B[(size_t)(k0 + bk) * N + n0 + bn];
        }

#pragma unroll
        for (int ks = 0; ks < 16; ks += 8) {
            uint2 a[2][4], bf[4][2];
            const int k0r = ks + tq;
            const int k1r = ks + tq + 4;
#pragma unroll
            for (int mi = 0; mi < 2; mi++) {
                const int r = wm + mi * 16 + g;
                a[mi][0] = As2[cur][k0r][swz(k0r, r)];
                a[mi][1] = As2[cur][k0r][swz(k0r, r + 8)];
                a[mi][2] = As2[cur][k1r][swz(k1r, r)];
                a[mi][3] = As2[cur][k1r][swz(k1r, r + 8)];
            }
#pragma unroll
            for (int ni = 0; ni < 4; ni++) {
                const int c = wn + ni * 8 + g;
                bf[ni][0] = Bs2[cur][k0r][swz(k0r, c)];
                bf[ni][1] = Bs2[cur][k1r][swz(k1r, c)];
            }
#pragma unroll
            for (int mi = 0; mi < 2; mi++) {
                const unsigned ah[4] = {a[mi][0].x, a[mi][1].x, a[mi][2].x, a[mi][3].x};
                const unsigned al[4] = {a[mi][0].y, a[mi][1].y, a[mi][2].y, a[mi][3].y};
#pragma unroll
                for (int ni = 0; ni < 4; ni++) {
                    const unsigned bh[2] = {bf[ni][0].x, bf[ni][1].x};
                    const unsigned bl[2] = {bf[ni][0].y, bf[ni][1].y};
                    // small terms first, hi*hi last
                    mma_tf32(acc[mi][ni], ah, bl);
                    mma_tf32(acc[mi][ni], al, bh);
                    mma_tf32(acc[mi][ni], ah, bh);
                }
            }
        }

        if (has_next) {
            const int nxt = cur ^ 1;
            As2[nxt][ak + 0][swz(ak + 0, am0)] = split_tf32(pa0.x);
            As2[nxt][ak + 1][swz(ak + 1, am0)] = split_tf32(pa0.y);
            As2[nxt][ak + 2][swz(ak + 2, am0)] = split_tf32(pa0.z);
            As2[nxt][ak + 3][swz(ak + 3, am0)] = split_tf32(pa0.w);
            As2[nxt][ak + 0][swz(ak + 0, am1)] = split_tf32(pa1.x);
            As2[nxt][ak + 1][swz(ak + 1, am1)] = split_tf32(pa1.y);
            As2[nxt][ak + 2][swz(ak + 2, am1)] = split_tf32(pa1.z);
            As2[nxt][ak + 3][swz(ak + 3, am1)] = split_tf32(pa1.w);
            if (MODE == 2) {
                Bs2[nxt][ck + 0][swz(ck + 0, cn)] = split_tf32(pb.x);
                Bs2[nxt][ck + 1][swz(ck + 1, cn)] = split_tf32(pb.y);
                Bs2[nxt][ck + 2][swz(ck + 2, cn)] = split_tf32(pb.z);
                Bs2[nxt][ck + 3][swz(ck + 3, cn)] = split_tf32(pb.w);
            } else {
                Bs2[nxt][bk][swz(bk, bn + 0)] = split_tf32(pb.x);
                Bs2[nxt][bk][swz(bk, bn + 1)] = split_tf32(pb.y);
                Bs2[nxt][bk][swz(bk, bn + 2)] = split_tf32(pb.z);
                Bs2[nxt][bk][swz(bk, bn + 3)] = split_tf32(pb.w);
            }
            __syncthreads();
        }
    }

    // ---- epilogue: c0,c1 at (row, col..col+1); c2,c3 at (row+8, ...) ----
    const float gm = (MODE == 1) ? gamma[0] : 0.0f;
    const float* Rp = (MODE == 1) ? res + (size_t)b * M * N : nullptr;
#pragma unroll
    for (int mi = 0; mi < 2; mi++) {
#pragma unroll
        for (int ni = 0; ni < 4; ni++) {
            const int row = m0 + wm + mi * 16 + g;
            const int col = n0 + wn + ni * 8 + 2 * tq;
            const float* a = acc[mi][ni];
            float2 v0, v1;
            if (MODE == 0) {
                const float b0 = bias[row], b1 = bias[row + 8];
                v0.x = a[0] + b0; v0.y = a[1] + b0;
                v1.x = a[2] + b1; v1.y = a[3] + b1;
            } else if (MODE == 1) {
                float2 r0 = *(const float2*)&Rp[(size_t)row * N + col];
                float2 r1 = *(const float2*)&Rp[(size_t)(row + 8) * N + col];
                v0.x = fmaf(gm, a[0], r0.x); v0.y = fmaf(gm, a[1], r0.y);
                v1.x = fmaf(gm, a[2], r1.x); v1.y = fmaf(gm, a[3], r1.y);
            } else {
                v0.x = a[0] * scale; v0.y = a[1] * scale;
                v1.x = a[2] * scale; v1.y = a[3] * scale;
            }
            *(float2*)&Cp[(size_t)row * N + col]       = v0;
            *(float2*)&Cp[(size_t)(row + 8) * N + col] = v1;
        }
    }
}

// ---------------------------------------------------------------------------
// Softmax over last dim (512). One block (128 threads) per row, 4 elems/thread.
// ---------------------------------------------------------------------------
__global__ __launch_bounds__(128)
void softmax512_kernel(float* __restrict__ data)
{
    __shared__ float red[4];
    float* p = data + (size_t)blockIdx.x * 512;
    const int t    = threadIdx.x;
    const int lane = t & 31;
    const int warp = t >> 5;

    float4 v = *(const float4*)&p[t << 2];

    float m = fmaxf(fmaxf(v.x, v.y), fmaxf(v.z, v.w));
#pragma unroll
    for (int o = 16; o > 0; o >>= 1)
        m = fmaxf(m, __shfl_xor_sync(0xffffffffu, m, o));
    if (lane == 0) red[warp] = m;
    __syncthreads();
    m = fmaxf(fmaxf(red[0], red[1]), fmaxf(red[2], red[3]));

    v.x = expf(v.x - m); v.y = expf(v.y - m);
    v.z = expf(v.z - m); v.w = expf(v.w - m);

    float s = v.x + v.y + v.z + v.w;
#pragma unroll
    for (int o = 16; o > 0; o >>= 1)
        s += __shfl_xor_sync(0xffffffffu, s, o);
    __syncthreads();
    if (lane == 0) red[warp] = s;
    __syncthreads();
    s = red[0] + red[1] + red[2] + red[3];

    const float inv = 1.0f / s;
    v.x *= inv; v.y *= inv; v.z *= inv; v.w *= inv;
    *(float4*)&p[t << 2] = v;
}

// ---------------------------------------------------------------------------
extern "C" void kernel_launch(void* const* d_in, const int* in_sizes, int n_in,
                              void* d_out, int out_size)
{
    const float* x      = (const float*)d_in[0];   // (16,512,64,64)
    const float* conv_w = (const float*)d_in[1];   // (256,512,1,1)
    const float* conv_b = (const float*)d_in[2];   // (256,)
    const float* gamma  = (const float*)d_in[3];   // (1,)
    float*       out    = (float*)d_out;           // (16,256,64,64)

    float* q    = nullptr;
    float* attn = nullptr;
    cudaGetSymbolAddress((void**)&q,    g_q);
    cudaGetSymbolAddress((void**)&attn, g_attn);

    // GEMM1: q = W @ x + bias   (M=256, N=4096, K=512)  2048 CTAs
    {
        dim3 grid(NHW / 64, NC1 / 128, NB);
        mma_gemm_kernel<0><<<grid, 256>>>(conv_w, x, conv_b, nullptr, nullptr,
                                          q, NC1, NHW, NC, 1.0f);
    }
    // GEMM2: energy = q @ x^T / 64  (M=256, N=512, K=4096)  256 CTAs
    {
        dim3 grid(NC / 64, NC1 / 128, NB);
        mma_gemm_kernel<2><<<grid, 256>>>(q, x, nullptr, nullptr, nullptr,
                                          attn, NC1, NC, NHW, 1.0f / 64.0f);
    }
    // softmax over C (512), in place
    softmax512_kernel<<<NB * NC1, 128>>>(attn);

    // GEMM3: out = gamma*(attn @ x) + q  (M=256, N=4096, K=512)
    {
        dim3 grid(NHW / 64, NC1 / 128, NB);
        mma_gemm_kernel<1><<<grid, 256>>>(attn, x, nullptr, gamma, q, out,
                                          NC1, NHW, NC, 1.0f);
    }
}

// round 10
// speedup vs baseline: 1.4017x; 1.4017x over previous
#include <cuda_runtime.h>

// CAM_Module channel attention. B=16, C=512, C1=256, HW=4096
//   q      = W[256,512] @ x_b[512,4096] + bias            (GEMM1, NN, 3xTF32)
//   energy = q[256,4096] @ x_b[512,4096]^T / 64           (GEMM2, NT, 1xTF32)
//   attn   = softmax(energy, last dim 512)
//   out    = gamma * (attn[256,512] @ x_b[512,4096]) + q  (GEMM3, NN, 1xTF32)
// GEMM1 keeps fp32-grade 3xTF32 (q is the dominant output term); GEMM2/3 run
// 1xTF32 (their error is ~10x diluted: |gamma*attn@x| ~ 0.1|q|, softmax damps
// GEMM2 further). W is pre-split once into scratch.

static constexpr int NB  = 16;
static constexpr int NC  = 512;
static constexpr int NC1 = 256;
static constexpr int NHW = 4096;

__device__ float g_q[(size_t)NB * NC1 * NHW];    // 64 MB scratch
__device__ float g_attn[(size_t)NB * NC1 * NC];  //  8 MB scratch
__device__ uint2 g_wsplit[NC1 * NC];             //  1 MB pre-split conv_w

__device__ __forceinline__ unsigned f2tf(float f) {
    unsigned u;
    asm("cvt.rna.tf32.f32 %0, %1;" : "=r"(u) : "f"(f));
    return u;
}

// Dekker split: v ~= hi + lo, both exactly representable in tf32.
__device__ __forceinline__ uint2 split_tf32(float v) {
    const unsigned hi = f2tf(v);
    const unsigned lo = f2tf(v - __uint_as_float(hi));
    return make_uint2(hi, lo);
}

// XOR swizzle on the m index (verified in R7): conflict-managed smem layout.
__device__ __forceinline__ int swz(int k, int m) {
    return m ^ ((((k & 3) ^ (k >> 2))) << 2);
}

__device__ __forceinline__ void mma_tf32(float* c, const unsigned* a, const unsigned* b) {
    asm volatile(
        "mma.sync.aligned.m16n8k8.row.col.f32.tf32.tf32.f32 "
        "{%0,%1,%2,%3}, {%4,%5,%6,%7}, {%8,%9}, {%0,%1,%2,%3};"
        : "+f"(c[0]), "+f"(c[1]), "+f"(c[2]), "+f"(c[3])
        : "r"(a[0]), "r"(a[1]), "r"(a[2]), "r"(a[3]),
          "r"(b[0]), "r"(b[1]));
}

// ---------------------------------------------------------------------------
// Pre-split conv_w into {hi,lo} tf32 pairs. 131072 elements.
// ---------------------------------------------------------------------------
__global__ void presplit_w_kernel(const float* __restrict__ w, uint2* __restrict__ o)
{
    const int i = blockIdx.x * blockDim.x + threadIdx.x;
    o[i] = split_tf32(w[i]);
}

// ---------------------------------------------------------------------------
// GEMM1 (3xTF32): q = W @ x + bias. BM=128 x BN=64 x BK=16, 256 threads,
// 8 warps (4x2), warp tile 32x32 = 2x4 m16n8k8. A = pre-split W (uint2 LDG).
// grid (NHW/64, NC1/128, NB)
// ---------------------------------------------------------------------------
__global__ __launch_bounds__(256, 2)
void gemm1_3x_kernel(const uint2* __restrict__ Wsp, const float* __restrict__ x,
                     const float* __restrict__ bias, float* __restrict__ Cout,
                     int M, int N, int K)
{
    const int b = blockIdx.z;
    const float* B = x + (size_t)b * K * N;
    float*      Cp = Cout + (size_t)b * M * N;

    __shared__ __align__(16) uint2 As2[2][16][128];  // 32 KB
    __shared__ __align__(16) uint2 Bs2[2][16][64];   // 16 KB

    const int t    = threadIdx.x;
    const int lane = t & 31;
    const int warp = t >> 5;
    const int wm   = (warp & 3) * 32;
    const int wn   = (warp >> 2) * 32;
    const int g    = lane >> 2;
    const int tq   = lane & 3;

    const int m0 = blockIdx.y * 128;
    const int n0 = blockIdx.x * 64;

    const int am0 = t >> 2;             // 0..63
    const int am1 = am0 + 64;
    const int ak  = (t & 3) << 2;       // 0,4,8,12
    const int bk  = t >> 4;             // 0..15
    const int bn  = (t & 15) << 2;      // 0..60

    float acc[2][4][4];
#pragma unroll
    for (int mi = 0; mi < 2; mi++)
#pragma unroll
        for (int ni = 0; ni < 4; ni++)
#pragma unroll
            for (int r = 0; r < 4; r++) acc[mi][ni][r] = 0.0f;

    const int nT = K >> 4;

    // prefetch tile 0 (A from pre-split W: uint4 = 2 uint2 elements)
    const uint4* W4 = (const uint4*)Wsp;
    uint4 wa0 = W4[((size_t)(m0 + am0) * K + ak) >> 1];
    uint4 wa1 = W4[(((size_t)(m0 + am0) * K + ak) >> 1) + 1];
    uint4 wb0 = W4[((size_t)(m0 + am1) * K + ak) >> 1];
    uint4 wb1 = W4[(((size_t)(m0 + am1) * K + ak) >> 1) + 1];
    float4 pb = *(const float4*)&B[(size_t)bk * N + n0 + bn];

    {
        As2[0][ak + 0][swz(ak + 0, am0)] = make_uint2(wa0.x, wa0.y);
        As2[0][ak + 1][swz(ak + 1, am0)] = make_uint2(wa0.z, wa0.w);
        As2[0][ak + 2][swz(ak + 2, am0)] = make_uint2(wa1.x, wa1.y);
        As2[0][ak + 3][swz(ak + 3, am0)] = make_uint2(wa1.z, wa1.w);
        As2[0][ak + 0][swz(ak + 0, am1)] = make_uint2(wb0.x, wb0.y);
        As2[0][ak + 1][swz(ak + 1, am1)] = make_uint2(wb0.z, wb0.w);
        As2[0][ak + 2][swz(ak + 2, am1)] = make_uint2(wb1.x, wb1.y);
        As2[0][ak + 3][swz(ak + 3, am1)] = make_uint2(wb1.z, wb1.w);
        Bs2[0][bk][swz(bk, bn + 0)] = split_tf32(pb.x);
        Bs2[0][bk][swz(bk, bn + 1)] = split_tf32(pb.y);
        Bs2[0][bk][swz(bk, bn + 2)] = split_tf32(pb.z);
        Bs2[0][bk][swz(bk, bn + 3)] = split_tf32(pb.w);
    }
    __syncthreads();

    for (int kt = 0; kt < nT; kt++) {
        const int  cur      = kt & 1;
        const bool has_next = (kt + 1 < nT);
        if (has_next) {
            const int k0 = (kt + 1) << 4;
            wa0 = W4[((size_t)(m0 + am0) * K + k0 + ak) >> 1];
            wa1 = W4[(((size_t)(m0 + am0) * K + k0 + ak) >> 1) + 1];
            wb0 = W4[((size_t)(m0 + am1) * K + k0 + ak) >> 1];
            wb1 = W4[(((size_t)(m0 + am1) * K + k0 + ak) >> 1) + 1];
            pb  = *(const float4*)&B[(size_t)(k0 + bk) * N + n0 + bn];
        }

#pragma unroll
        for (int ks = 0; ks < 16; ks += 8) {
            uint2 a[2][4], bf[4][2];
            const int k0r = ks + tq;
            const int k1r = ks + tq + 4;
#pragma unroll
            for (int mi = 0; mi < 2; mi++) {
                const int r = wm + mi * 16 + g;
                a[mi][0] = As2[cur][k0r][swz(k0r, r)];
                a[mi][1] = As2[cur][k0r][swz(k0r, r + 8)];
                a[mi][2] = As2[cur][k1r][swz(k1r, r)];
                a[mi][3] = As2[cur][k1r][swz(k1r, r + 8)];
            }
#pragma unroll
            for (int ni = 0; ni < 4; ni++) {
                const int c = wn + ni * 8 + g;
                bf[ni][0] = Bs2[cur][k0r][swz(k0r, c)];
                bf[ni][1] = Bs2[cur][k1r][swz(k1r, c)];
            }
#pragma unroll
            for (int mi = 0; mi < 2; mi++) {
                const unsigned ah[4] = {a[mi][0].x, a[mi][1].x, a[mi][2].x, a[mi][3].x};
                const unsigned al[4] = {a[mi][0].y, a[mi][1].y, a[mi][2].y, a[mi][3].y};
#pragma unroll
                for (int ni = 0; ni < 4; ni++) {
                    const unsigned bh[2] = {bf[ni][0].x, bf[ni][1].x};
                    const unsigned bl[2] = {bf[ni][0].y, bf[ni][1].y};
                    mma_tf32(acc[mi][ni], ah, bl);
                    mma_tf32(acc[mi][ni], al, bh);
                    mma_tf32(acc[mi][ni], ah, bh);
                }
            }
        }

        if (has_next) {
            const int nxt = cur ^ 1;
            As2[nxt][ak + 0][swz(ak + 0, am0)] = make_uint2(wa0.x, wa0.y);
            As2[nxt][ak + 1][swz(ak + 1, am0)] = make_uint2(wa0.z, wa0.w);
            As2[nxt][ak + 2][swz(ak + 2, am0)] = make_uint2(wa1.x, wa1.y);
            As2[nxt][ak + 3][swz(ak + 3, am0)] = make_uint2(wa1.z, wa1.w);
            As2[nxt][ak + 0][swz(ak + 0, am1)] = make_uint2(wb0.x, wb0.y);
            As2[nxt][ak + 1][swz(ak + 1, am1)] = make_uint2(wb0.z, wb0.w);
            As2[nxt][ak + 2][swz(ak + 2, am1)] = make_uint2(wb1.x, wb1.y);
            As2[nxt][ak + 3][swz(ak + 3, am1)] = make_uint2(wb1.z, wb1.w);
            Bs2[nxt][bk][swz(bk, bn + 0)] = split_tf32(pb.x);
            Bs2[nxt][bk][swz(bk, bn + 1)] = split_tf32(pb.y);
            Bs2[nxt][bk][swz(bk, bn + 2)] = split_tf32(pb.z);
            Bs2[nxt][bk][swz(bk, bn + 3)] = split_tf32(pb.w);
            __syncthreads();
        }
    }

    // epilogue: + bias
#pragma unroll
    for (int mi = 0; mi < 2; mi++) {
#pragma unroll
        for (int ni = 0; ni < 4; ni++) {
            const int row = m0 + wm + mi * 16 + g;
            const int col = n0 + wn + ni * 8 + 2 * tq;
            const float* a = acc[mi][ni];
            const float b0 = bias[row], b1 = bias[row + 8];
            float2 v0 = make_float2(a[0] + b0, a[1] + b0);
            float2 v1 = make_float2(a[2] + b1, a[3] + b1);
            *(float2*)&Cp[(size_t)row * N + col]       = v0;
            *(float2*)&Cp[(size_t)(row + 8) * N + col] = v1;
        }
    }
}

// ---------------------------------------------------------------------------
// 1xTF32 GEMM (GEMM2/GEMM3): same tiling, plain-uint smem (hi only).
// MODE 1: NN, A per-batch (attn), C = gamma*(A@B) + res
// MODE 2: NT, A per-batch (q), B=[N,K] row-major, C = scale*(A@B^T)
// grid (N/64, M/128, batch)
// ---------------------------------------------------------------------------
template <int MODE>
__global__ __launch_bounds__(256, 2)
void mma_gemm1x_kernel(const float* __restrict__ A_, const float* __restrict__ x,
                       const float* __restrict__ gamma, const float* __restrict__ res,
                       float* __restrict__ Cout, int M, int N, int K, float scale)
{
    const int b = blockIdx.z;
    const float* A = A_ + (size_t)b * M * K;
    const float* B = (MODE == 2) ? x + (size_t)b * N * K : x + (size_t)b * K * N;
    float*      Cp = Cout + (size_t)b * M * N;

    __shared__ __align__(16) unsigned As1[2][16][128];  // 16 KB
    __shared__ __align__(16) unsigned Bs1[2][16][64];   //  8 KB

    const int t    = threadIdx.x;
    const int lane = t & 31;
    const int warp = t >> 5;
    const int wm   = (warp & 3) * 32;
    const int wn   = (warp >> 2) * 32;
    const int g    = lane >> 2;
    const int tq   = lane & 3;

    const int m0 = blockIdx.y * 128;
    const int n0 = blockIdx.x * 64;

    const int am0 = t >> 2;
    const int am1 = am0 + 64;
    const int ak  = (t & 3) << 2;
    const int bk  = t >> 4;
    const int bn  = (t & 15) << 2;
    const int cn  = t >> 2;
    const int ck  = (t & 3) << 2;

    float acc[2][4][4];
#pragma unroll
    for (int mi = 0; mi < 2; mi++)
#pragma unroll
        for (int ni = 0; ni < 4; ni++)
#pragma unroll
            for (int r = 0; r < 4; r++) acc[mi][ni][r] = 0.0f;

    const int nT = K >> 4;

    float4 pa0 = *(const float4*)&A[(size_t)(m0 + am0) * K + ak];
    float4 pa1 = *(const float4*)&A[(size_t)(m0 + am1) * K + ak];
    float4 pb;
    if (MODE == 2) pb = *(const float4*)&B[(size_t)(n0 + cn) * K + ck];
    else           pb = *(const float4*)&B[(size_t)bk * N + n0 + bn];

    {
        As1[0][ak + 0][swz(ak + 0, am0)] = f2tf(pa0.x);
        As1[0][ak + 1][swz(ak + 1, am0)] = f2tf(pa0.y);
        As1[0][ak + 2][swz(ak + 2, am0)] = f2tf(pa0.z);
        As1[0][ak + 3][swz(ak + 3, am0)] = f2tf(pa0.w);
        As1[0][ak + 0][swz(ak + 0, am1)] = f2tf(pa1.x);
        As1[0][ak + 1][swz(ak + 1, am1)] = f2tf(pa1.y);
        As1[0][ak + 2][swz(ak + 2, am1)] = f2tf(pa1.z);
        As1[0][ak + 3][swz(ak + 3, am1)] = f2tf(pa1.w);
        if (MODE == 2) {
            Bs1[0][ck + 0][swz(ck + 0, cn)] = f2tf(pb.x);
            Bs1[0][ck + 1][swz(ck + 1, cn)] = f2tf(pb.y);
            Bs1[0][ck + 2][swz(ck + 2, cn)] = f2tf(pb.z);
            Bs1[0][ck + 3][swz(ck + 3, cn)] = f2tf(pb.w);
        } else {
            Bs1[0][bk][swz(bk, bn + 0)] = f2tf(pb.x);
            Bs1[0][bk][swz(bk, bn + 1)] = f2tf(pb.y);
            Bs1[0][bk][swz(bk, bn + 2)] = f2tf(pb.z);
            Bs1[0][bk][swz(bk, bn + 3)] = f2tf(pb.w);
        }
    }
    __syncthreads();

    for (int kt = 0; kt < nT; kt++) {
        const int  cur      = kt & 1;
        const bool has_next = (kt + 1 < nT);
        if (has_next) {
            const int k0 = (kt + 1) << 4;
            pa0 = *(const float4*)&A[(size_t)(m0 + am0) * K + k0 + ak];
            pa1 = *(const float4*)&A[(size_t)(m0 + am1) * K + k0 + ak];
            if (MODE == 2) pb = *(const float4*)&B[(size_t)(n0 + cn) * K + k0 + ck];
            else           pb = *(const float4*)&B[(size_t)(k0 + bk) * N + n0 + bn];
        }

#pragma unroll
        for (int ks = 0; ks < 16; ks += 8) {
            unsigned a[2][4], bf[4][2];
            const int k0r = ks + tq;
            const int k1r = ks + tq + 4;
#pragma unroll
            for (int mi = 0; mi < 2; mi++) {
                const int r = wm + mi * 16 + g;
                a[mi][0] = As1[cur][k0r][swz(k0r, r)];
                a[mi][1] = As1[cur][k0r][swz(k0r, r + 8)];
                a[mi][2] = As1[cur][k1r][swz(k1r, r)];
                a[mi][3] = As1[cur][k1r][swz(k1r, r + 8)];
            }
#pragma unroll
            for (int ni = 0; ni < 4; ni++) {
                const int c = wn + ni * 8 + g;
                bf[ni][0] = Bs1[cur][k0r][swz(k0r, c)];
                bf[ni][1] = Bs1[cur][k1r][swz(k1r, c)];
            }
#pragma unroll
            for (int mi = 0; mi < 2; mi++)
#pragma unroll
                for (int ni = 0; ni < 4; ni++)
                    mma_tf32(acc[mi][ni], a[mi], bf[ni]);
        }

        if (has_next) {
            const int nxt = cur ^ 1;
            As1[nxt][ak + 0][swz(ak + 0, am0)] = f2tf(pa0.x);
            As1[nxt][ak + 1][swz(ak + 1, am0)] = f2tf(pa0.y);
            As1[nxt][ak + 2][swz(ak + 2, am0)] = f2tf(pa0.z);
            As1[nxt][ak + 3][swz(ak + 3, am0)] = f2tf(pa0.w);
            As1[nxt][ak + 0][swz(ak + 0, am1)] = f2tf(pa1.x);
            As1[nxt][ak + 1][swz(ak + 1, am1)] = f2tf(pa1.y);
            As1[nxt][ak + 2][swz(ak + 2, am1)] = f2tf(pa1.z);
            As1[nxt][ak + 3][swz(ak + 3, am1)] = f2tf(pa1.w);
            if (MODE == 2) {
                Bs1[nxt][ck + 0][swz(ck + 0, cn)] = f2tf(pb.x);
                Bs1[nxt][ck + 1][swz(ck + 1, cn)] = f2tf(pb.y);
                Bs1[nxt][ck + 2][swz(ck + 2, cn)] = f2tf(pb.z);
                Bs1[nxt][ck + 3][swz(ck + 3, cn)] = f2tf(pb.w);
            } else {
                Bs1[nxt][bk][swz(bk, bn + 0)] = f2tf(pb.x);
                Bs1[nxt][bk][swz(bk, bn + 1)] = f2tf(pb.y);
                Bs1[nxt][bk][swz(bk, bn + 2)] = f2tf(pb.z);
                Bs1[nxt][bk][swz(bk, bn + 3)] = f2tf(pb.w);
            }
            __syncthreads();
        }
    }

    const float gm = (MODE == 1) ? gamma[0] : 0.0f;
    const float* Rp = (MODE == 1) ? res + (size_t)b * M * N : nullptr;
#pragma unroll
    for (int mi = 0; mi < 2; mi++) {
#pragma unroll
        for (int ni = 0; ni < 4; ni++) {
            const int row = m0 + wm + mi * 16 + g;
            const int col = n0 + wn + ni * 8 + 2 * tq;
            const float* a = acc[mi][ni];
            float2 v0, v1;
            if (MODE == 1) {
                float2 r0 = *(const float2*)&Rp[(size_t)row * N + col];
                float2 r1 = *(const float2*)&Rp[(size_t)(row + 8) * N + col];
                v0.x = fmaf(gm, a[0], r0.x); v0.y = fmaf(gm, a[1], r0.y);
                v1.x = fmaf(gm, a[2], r1.x); v1.y = fmaf(gm, a[3], r1.y);
            } else {
                v0.x = a[0] * scale; v0.y = a[1] * scale;
                v1.x = a[2] * scale; v1.y = a[3] * scale;
            }
            *(float2*)&Cp[(size_t)row * N + col]       = v0;
            *(float2*)&Cp[(size_t)(row + 8) * N + col] = v1;
        }
    }
}

// ---------------------------------------------------------------------------
// Softmax over last dim (512). One block (128 threads) per row, 4 elems/thread.
// ---------------------------------------------------------------------------
__global__ __launch_bounds__(128)
void softmax512_kernel(float* __restrict__ data)
{
    __shared__ float red[4];
    float* p = data + (size_t)blockIdx.x * 512;
    const int t    = threadIdx.x;
    const int lane = t & 31;
    const int warp = t >> 5;

    float4 v = *(const float4*)&p[t << 2];

    float m = fmaxf(fmaxf(v.x, v.y), fmaxf(v.z, v.w));
#pragma unroll
    for (int o = 16; o > 0; o >>= 1)
        m = fmaxf(m, __shfl_xor_sync(0xffffffffu, m, o));
    if (lane == 0) red[warp] = m;
    __syncthreads();
    m = fmaxf(fmaxf(red[0], red[1]), fmaxf(red[2], red[3]));

    v.x = expf(v.x - m); v.y = expf(v.y - m);
    v.z = expf(v.z - m); v.w = expf(v.w - m);

    float s = v.x + v.y + v.z + v.w;
#pragma unroll
    for (int o = 16; o > 0; o >>= 1)
        s += __shfl_xor_sync(0xffffffffu, s, o);
    __syncthreads();
    if (lane == 0) red[warp] = s;
    __syncthreads();
    s = red[0] + red[1] + red[2] + red[3];

    const float inv = 1.0f / s;
    v.x *= inv; v.y *= inv; v.z *= inv; v.w *= inv;
    *(float4*)&p[t << 2] = v;
}

// ---------------------------------------------------------------------------
extern "C" void kernel_launch(void* const* d_in, const int* in_sizes, int n_in,
                              void* d_out, int out_size)
{
    const float* x      = (const float*)d_in[0];   // (16,512,64,64)
    const float* conv_w = (const float*)d_in[1];   // (256,512,1,1)
    const float* conv_b = (const float*)d_in[2];   // (256,)
    const float* gamma  = (const float*)d_in[3];   // (1,)
    float*       out    = (float*)d_out;           // (16,256,64,64)

    float* q    = nullptr;
    float* attn = nullptr;
    uint2* wsp  = nullptr;
    cudaGetSymbolAddress((void**)&q,    g_q);
    cudaGetSymbolAddress((void**)&attn, g_attn);
    cudaGetSymbolAddress((void**)&wsp,  g_wsplit);

    // Pre-split W (256*512 = 131072 elements)
    presplit_w_kernel<<<512, 256>>>(conv_w, wsp);

    // GEMM1: q = W @ x + bias   (M=256, N=4096, K=512)  3xTF32
    {
        dim3 grid(NHW / 64, NC1 / 128, NB);
        gemm1_3x_kernel<<<grid, 256>>>(wsp, x, conv_b, q, NC1, NHW, NC);
    }
    // GEMM2: energy = q @ x^T / 64  (M=256, N=512, K=4096)  1xTF32
    {
        dim3 grid(NC / 64, NC1 / 128, NB);
        mma_gemm1x_kernel<2><<<grid, 256>>>(q, x, nullptr, nullptr, attn,
                                            NC1, NC, NHW, 1.0f / 64.0f);
    }
    // softmax over C (512), in place
    softmax512_kernel<<<NB * NC1, 128>>>(attn);

    // GEMM3: out = gamma*(attn @ x) + q  (M=256, N=4096, K=512)  1xTF32
    {
        dim3 grid(NHW / 64, NC1 / 128, NB);
        mma_gemm1x_kernel<1><<<grid, 256>>>(attn, x, gamma, q, out,
                                            NC1, NHW, NC, 1.0f);
    }
}

// round 12
// speedup vs baseline: 1.4843x; 1.0589x over previous
#include <cuda_runtime.h>

// CAM_Module channel attention. B=16, C=512, C1=256, HW=4096
//   q      = W[256,512] @ x_b[512,4096] + bias            (GEMM1, NN, 3xTF32)
//   energy = q[256,4096] @ x_b[512,4096]^T / 64           (GEMM2, NT, 1xTF32)
//   attn   = softmax(energy, last dim 512)
//   out    = gamma * (attn[256,512] @ x_b[512,4096]) + q  (GEMM3, NN, 1xTF32)
// GEMM1: 3xTF32 (q error hits output 1:1; measured: 1x undiluted ~8e-4).
// GEMM2/3: 1xTF32 (error ~10x diluted; measured contribution ~8e-5).
// 1x kernels: 128x128 block / 64x32 warp tiles (higher MMA:overhead ratio).

static constexpr int NB  = 16;
static constexpr int NC  = 512;
static constexpr int NC1 = 256;
static constexpr int NHW = 4096;

__device__ float g_q[(size_t)NB * NC1 * NHW];    // 64 MB scratch
__device__ float g_attn[(size_t)NB * NC1 * NC];  //  8 MB scratch
__device__ uint2 g_wsplit[NC1 * NC];             //  1 MB pre-split conv_w

__device__ __forceinline__ unsigned f2tf(float f) {
    unsigned u;
    asm("cvt.rna.tf32.f32 %0, %1;" : "=r"(u) : "f"(f));
    return u;
}

// Dekker split: v ~= hi + lo, both exactly representable in tf32.
__device__ __forceinline__ uint2 split_tf32(float v) {
    const unsigned hi = f2tf(v);
    const unsigned lo = f2tf(v - __uint_as_float(hi));
    return make_uint2(hi, lo);
}

// XOR swizzle on the m index (verified R7/R10): conflict-managed smem layout.
__device__ __forceinline__ int swz(int k, int m) {
    return m ^ ((((k & 3) ^ (k >> 2))) << 2);
}

__device__ __forceinline__ void mma_tf32(float* c, const unsigned* a, const unsigned* b) {
    asm volatile(
        "mma.sync.aligned.m16n8k8.row.col.f32.tf32.tf32.f32 "
        "{%0,%1,%2,%3}, {%4,%5,%6,%7}, {%8,%9}, {%0,%1,%2,%3};"
        : "+f"(c[0]), "+f"(c[1]), "+f"(c[2]), "+f"(c[3])
        : "r"(a[0]), "r"(a[1]), "r"(a[2]), "r"(a[3]),
          "r"(b[0]), "r"(b[1]));
}

// ---------------------------------------------------------------------------
// Pre-split conv_w into {hi,lo} tf32 pairs. 131072 elements.
// ---------------------------------------------------------------------------
__global__ void presplit_w_kernel(const float* __restrict__ w, uint2* __restrict__ o)
{
    const int i = blockIdx.x * blockDim.x + threadIdx.x;
    o[i] = split_tf32(w[i]);
}

// ---------------------------------------------------------------------------
// GEMM1 (3xTF32): q = W @ x + bias. BM=128 x BN=64 x BK=16, 256 threads,
// 8 warps (4x2), warp tile 32x32. A = pre-split W (uint2 LDG).
// [UNCHANGED from R10-verified version.]
// grid (NHW/64, NC1/128, NB)
// ---------------------------------------------------------------------------
__global__ __launch_bounds__(256, 2)
void gemm1_3x_kernel(const uint2* __restrict__ Wsp, const float* __restrict__ x,
                     const float* __restrict__ bias, float* __restrict__ Cout,
                     int M, int N, int K)
{
    const int b = blockIdx.z;
    const float* B = x + (size_t)b * K * N;
    float*      Cp = Cout + (size_t)b * M * N;

    __shared__ __align__(16) uint2 As2[2][16][128];  // 32 KB
    __shared__ __align__(16) uint2 Bs2[2][16][64];   // 16 KB

    const int t    = threadIdx.x;
    const int lane = t & 31;
    const int warp = t >> 5;
    const int wm   = (warp & 3) * 32;
    const int wn   = (warp >> 2) * 32;
    const int g    = lane >> 2;
    const int tq   = lane & 3;

    const int m0 = blockIdx.y * 128;
    const int n0 = blockIdx.x * 64;

    const int am0 = t >> 2;             // 0..63
    const int am1 = am0 + 64;
    const int ak  = (t & 3) << 2;       // 0,4,8,12
    const int bk  = t >> 4;             // 0..15
    const int bn  = (t & 15) << 2;      // 0..60

    float acc[2][4][4];
#pragma unroll
    for (int mi = 0; mi < 2; mi++)
#pragma unroll
        for (int ni = 0; ni < 4; ni++)
#pragma unroll
            for (int r = 0; r < 4; r++) acc[mi][ni][r] = 0.0f;

    const int nT = K >> 4;

    const uint4* W4 = (const uint4*)Wsp;
    uint4 wa0 = W4[((size_t)(m0 + am0) * K + ak) >> 1];
    uint4 wa1 = W4[(((size_t)(m0 + am0) * K + ak) >> 1) + 1];
    uint4 wb0 = W4[((size_t)(m0 + am1) * K + ak) >> 1];
    uint4 wb1 = W4[(((size_t)(m0 + am1) * K + ak) >> 1) + 1];
    float4 pb = *(const float4*)&B[(size_t)bk * N + n0 + bn];

    {
        As2[0][ak + 0][swz(ak + 0, am0)] = make_uint2(wa0.x, wa0.y);
        As2[0][ak + 1][swz(ak + 1, am0)] = make_uint2(wa0.z, wa0.w);
        As2[0][ak + 2][swz(ak + 2, am0)] = make_uint2(wa1.x, wa1.y);
        As2[0][ak + 3][swz(ak + 3, am0)] = make_uint2(wa1.z, wa1.w);
        As2[0][ak + 0][swz(ak + 0, am1)] = make_uint2(wb0.x, wb0.y);
        As2[0][ak + 1][swz(ak + 1, am1)] = make_uint2(wb0.z, wb0.w);
        As2[0][ak + 2][swz(ak + 2, am1)] = make_uint2(wb1.x, wb1.y);
        As2[0][ak + 3][swz(ak + 3, am1)] = make_uint2(wb1.z, wb1.w);
        Bs2[0][bk][swz(bk, bn + 0)] = split_tf32(pb.x);
        Bs2[0][bk][swz(bk, bn + 1)] = split_tf32(pb.y);
        Bs2[0][bk][swz(bk, bn + 2)] = split_tf32(pb.z);
        Bs2[0][bk][swz(bk, bn + 3)] = split_tf32(pb.w);
    }
    __syncthreads();

    for (int kt = 0; kt < nT; kt++) {
        const int  cur      = kt & 1;
        const bool has_next = (kt + 1 < nT);
        if (has_next) {
            const int k0 = (kt + 1) << 4;
            wa0 = W4[((size_t)(m0 + am0) * K + k0 + ak) >> 1];
            wa1 = W4[(((size_t)(m0 + am0) * K + k0 + ak) >> 1) + 1];
            wb0 = W4[((size_t)(m0 + am1) * K + k0 + ak) >> 1];
            wb1 = W4[(((size_t)(m0 + am1) * K + k0 + ak) >> 1) + 1];
            pb  = *(const float4*)&B[(size_t)(k0 + bk) * N + n0 + bn];
        }

#pragma unroll
        for (int ks = 0; ks < 16; ks += 8) {
            uint2 a[2][4], bf[4][2];
            const int k0r = ks + tq;
            const int k1r = ks + tq + 4;
#pragma unroll
            for (int mi = 0; mi < 2; mi++) {
                const int r = wm + mi * 16 + g;
                a[mi][0] = As2[cur][k0r][swz(k0r, r)];
                a[mi][1] = As2[cur][k0r][swz(k0r, r + 8)];
                a[mi][2] = As2[cur][k1r][swz(k1r, r)];
                a[mi][3] = As2[cur][k1r][swz(k1r, r + 8)];
            }
#pragma unroll
            for (int ni = 0; ni < 4; ni++) {
                const int c = wn + ni * 8 + g;
                bf[ni][0] = Bs2[cur][k0r][swz(k0r, c)];
                bf[ni][1] = Bs2[cur][k1r][swz(k1r, c)];
            }
#pragma unroll
            for (int mi = 0; mi < 2; mi++) {
                const unsigned ah[4] = {a[mi][0].x, a[mi][1].x, a[mi][2].x, a[mi][3].x};
                const unsigned al[4] = {a[mi][0].y, a[mi][1].y, a[mi][2].y, a[mi][3].y};
#pragma unroll
                for (int ni = 0; ni < 4; ni++) {
                    const unsigned bh[2] = {bf[ni][0].x, bf[ni][1].x};
                    const unsigned bl[2] = {bf[ni][0].y, bf[ni][1].y};
                    mma_tf32(acc[mi][ni], ah, bl);
                    mma_tf32(acc[mi][ni], al, bh);
                    mma_tf32(acc[mi][ni], ah, bh);
                }
            }
        }

        if (has_next) {
            const int nxt = cur ^ 1;
            As2[nxt][ak + 0][swz(ak + 0, am0)] = make_uint2(wa0.x, wa0.y);
            As2[nxt][ak + 1][swz(ak + 1, am0)] = make_uint2(wa0.z, wa0.w);
            As2[nxt][ak + 2][swz(ak + 2, am0)] = make_uint2(wa1.x, wa1.y);
            As2[nxt][ak + 3][swz(ak + 3, am0)] = make_uint2(wa1.z, wa1.w);
            As2[nxt][ak + 0][swz(ak + 0, am1)] = make_uint2(wb0.x, wb0.y);
            As2[nxt][ak + 1][swz(ak + 1, am1)] = make_uint2(wb0.z, wb0.w);
            As2[nxt][ak + 2][swz(ak + 2, am1)] = make_uint2(wb1.x, wb1.y);
            As2[nxt][ak + 3][swz(ak + 3, am1)] = make_uint2(wb1.z, wb1.w);
            Bs2[nxt][bk][swz(bk, bn + 0)] = split_tf32(pb.x);
            Bs2[nxt][bk][swz(bk, bn + 1)] = split_tf32(pb.y);
            Bs2[nxt][bk][swz(bk, bn + 2)] = split_tf32(pb.z);
            Bs2[nxt][bk][swz(bk, bn + 3)] = split_tf32(pb.w);
            __syncthreads();
        }
    }

#pragma unroll
    for (int mi = 0; mi < 2; mi++) {
#pragma unroll
        for (int ni = 0; ni < 4; ni++) {
            const int row = m0 + wm + mi * 16 + g;
            const int col = n0 + wn + ni * 8 + 2 * tq;
            const float* a = acc[mi][ni];
            const float b0 = bias[row], b1 = bias[row + 8];
            float2 v0 = make_float2(a[0] + b0, a[1] + b0);
            float2 v1 = make_float2(a[2] + b1, a[3] + b1);
            *(float2*)&Cp[(size_t)row * N + col]       = v0;
            *(float2*)&Cp[(size_t)(row + 8) * N + col] = v1;
        }
    }
}

// ---------------------------------------------------------------------------
// 1xTF32 GEMM (GEMM2/GEMM3): BM=128 x BN=128 x BK=16, 256 threads,
// 8 warps (2 M x 4 N), warp tile 64x32 = 4x4 m16n8k8.
// MODE 1: NN, A per-batch (attn), C = gamma*(A@B) + res
// MODE 2: NT, A per-batch (q), B=[N,K] row-major, C = scale*(A@B^T)
// grid (N/128, M/128, batch)
// ---------------------------------------------------------------------------
template <int MODE>
__global__ __launch_bounds__(256, 2)
void mma_gemm1x_kernel(const float* __restrict__ A_, const float* __restrict__ x,
                       const float* __restrict__ gamma, const float* __restrict__ res,
                       float* __restrict__ Cout, int M, int N, int K, float scale)
{
    const int b = blockIdx.z;
    const float* A = A_ + (size_t)b * M * K;
    const float* B = (MODE == 2) ? x + (size_t)b * N * K : x + (size_t)b * K * N;
    float*      Cp = Cout + (size_t)b * M * N;

    __shared__ __align__(16) unsigned As1[2][16][128];  // 16 KB
    __shared__ __align__(16) unsigned Bs1[2][16][128];  // 16 KB

    const int t    = threadIdx.x;
    const int lane = t & 31;
    const int warp = t >> 5;
    const int wm   = (warp & 1) * 64;   // 2 m-groups of 64
    const int wn   = (warp >> 1) * 32;  // 4 n-groups of 32
    const int g    = lane >> 2;
    const int tq   = lane & 3;

    const int m0 = blockIdx.y * 128;
    const int n0 = blockIdx.x * 128;

    // A tile 128(m) x 16(k): 2 float4/thread along K
    const int am = t >> 1;              // 0..127
    const int ak = (t & 1) << 3;        // 0 or 8
    // B NN tile 16(k) x 128(n): 2 float4/thread along N
    const int bk = t >> 4;              // 0..15
    const int bn = (t & 15) << 3;       // 0..120
    // B NT tile 128(n rows) x 16(k): 2 float4/thread along K
    const int cn = t >> 1;              // 0..127
    const int ck = (t & 1) << 3;        // 0 or 8

    float acc[4][4][4];
#pragma unroll
    for (int mi = 0; mi < 4; mi++)
#pragma unroll
        for (int ni = 0; ni < 4; ni++)
#pragma unroll
            for (int r = 0; r < 4; r++) acc[mi][ni][r] = 0.0f;

    const int nT = K >> 4;

    float4 pa0 = *(const float4*)&A[(size_t)(m0 + am) * K + ak];
    float4 pa1 = *(const float4*)&A[(size_t)(m0 + am) * K + ak + 4];
    float4 pb0, pb1;
    if (MODE == 2) {
        pb0 = *(const float4*)&B[(size_t)(n0 + cn) * K + ck];
        pb1 = *(const float4*)&B[(size_t)(n0 + cn) * K + ck + 4];
    } else {
        pb0 = *(const float4*)&B[(size_t)bk * N + n0 + bn];
        pb1 = *(const float4*)&B[(size_t)bk * N + n0 + bn + 4];
    }

    {
        As1[0][ak + 0][swz(ak + 0, am)] = f2tf(pa0.x);
        As1[0][ak + 1][swz(ak + 1, am)] = f2tf(pa0.y);
        As1[0][ak + 2][swz(ak + 2, am)] = f2tf(pa0.z);
        As1[0][ak + 3][swz(ak + 3, am)] = f2tf(pa0.w);
        As1[0][ak + 4][swz(ak + 4, am)] = f2tf(pa1.x);
        As1[0][ak + 5][swz(ak + 5, am)] = f2tf(pa1.y);
        As1[0][ak + 6][swz(ak + 6, am)] = f2tf(pa1.z);
        As1[0][ak + 7][swz(ak + 7, am)] = f2tf(pa1.w);
        if (MODE == 2) {
            Bs1[0][ck + 0][swz(ck + 0, cn)] = f2tf(pb0.x);
            Bs1[0][ck + 1][swz(ck + 1, cn)] = f2tf(pb0.y);
            Bs1[0][ck + 2][swz(ck + 2, cn)] = f2tf(pb0.z);
            Bs1[0][ck + 3][swz(ck + 3, cn)] = f2tf(pb0.w);
            Bs1[0][ck + 4][swz(ck + 4, cn)] = f2tf(pb1.x);
            Bs1[0][ck + 5][swz(ck + 5, cn)] = f2tf(pb1.y);
            Bs1[0][ck + 6][swz(ck + 6, cn)] = f2tf(pb1.z);
            Bs1[0][ck + 7][swz(ck + 7, cn)] = f2tf(pb1.w);
        } else {
            uint4 u0 = make_uint4(f2tf(pb0.x), f2tf(pb0.y), f2tf(pb0.z), f2tf(pb0.w));
            uint4 u1 = make_uint4(f2tf(pb1.x), f2tf(pb1.y), f2tf(pb1.z), f2tf(pb1.w));
            *(uint4*)&Bs1[0][bk][swz(bk, bn)]     = u0;
            *(uint4*)&Bs1[0][bk][swz(bk, bn + 4)] = u1;
        }
    }
    __syncthreads();

    for (int kt = 0; kt < nT; kt++) {
        const int  cur      = kt & 1;
        const bool has_next = (kt + 1 < nT);
        if (has_next) {
            const int k0 = (kt + 1) << 4;
            pa0 = *(const float4*)&A[(size_t)(m0 + am) * K + k0 + ak];
            pa1 = *(const float4*)&A[(size_t)(m0 + am) * K + k0 + ak + 4];
            if (MODE == 2) {
                pb0 = *(const float4*)&B[(size_t)(n0 + cn) * K + k0 + ck];
                pb1 = *(const float4*)&B[(size_t)(n0 + cn) * K + k0 + ck + 4];
            } else {
                pb0 = *(const float4*)&B[(size_t)(k0 + bk) * N + n0 + bn];
                pb1 = *(const float4*)&B[(size_t)(k0 + bk) * N + n0 + bn + 4];
            }
        }

#pragma unroll
        for (int ks = 0; ks < 16; ks += 8) {
            unsigned a[4][4], bf[4][2];
            const int k0r = ks + tq;
            const int k1r = ks + tq + 4;
#pragma unroll
            for (int mi = 0; mi < 4; mi++) {
                const int r = wm + mi * 16 + g;
                a[mi][0] = As1[cur][k0r][swz(k0r, r)];
                a[mi][1] = As1[cur][k0r][swz(k0r, r + 8)];
                a[mi][2] = As1[cur][k1r][swz(k1r, r)];
                a[mi][3] = As1[cur][k1r][swz(k1r, r + 8)];
            }
#pragma unroll
            for (int ni = 0; ni < 4; ni++) {
                const int c = wn + ni * 8 + g;
                bf[ni][0] = Bs1[cur][k0r][swz(k0r, c)];
                bf[ni][1] = Bs1[cur][k1r][swz(k1r, c)];
            }
#pragma unroll
            for (int mi = 0; mi < 4; mi++)
#pragma unroll
                for (int ni = 0; ni < 4; ni++)
                    mma_tf32(acc[mi][ni], a[mi], bf[ni]);
        }

        if (has_next) {
            const int nxt = cur ^ 1;
            As1[nxt][ak + 0][swz(ak + 0, am)] = f2tf(pa0.x);
            As1[nxt][ak + 1][swz(ak + 1, am)] = f2tf(pa0.y);
            As1[nxt][ak + 2][swz(ak + 2, am)] = f2tf(pa0.z);
            As1[nxt][ak + 3][swz(ak + 3, am)] = f2tf(pa0.w);
            As1[nxt][ak + 4][swz(ak + 4, am)] = f2tf(pa1.x);
            As1[nxt][ak + 5][swz(ak + 5, am)] = f2tf(pa1.y);
            As1[nxt][ak + 6][swz(ak + 6, am)] = f2tf(pa1.z);
            As1[nxt][ak + 7][swz(ak + 7, am)] = f2tf(pa1.w);
            if (MODE == 2) {
                Bs1[nxt][ck + 0][swz(ck + 0, cn)] = f2tf(pb0.x);
                Bs1[nxt][ck + 1][swz(ck + 1, cn)] = f2tf(pb0.y);
                Bs1[nxt][ck + 2][swz(ck + 2, cn)] = f2tf(pb0.z);
                Bs1[nxt][ck + 3][swz(ck + 3, cn)] = f2tf(pb0.w);
                Bs1[nxt][ck + 4][swz(ck + 4, cn)] = f2tf(pb1.x);
                Bs1[nxt][ck + 5][swz(ck + 5, cn)] = f2tf(pb1.y);
                Bs1[nxt][ck + 6][swz(ck + 6, cn)] = f2tf(pb1.z);
                Bs1[nxt][ck + 7][swz(ck + 7, cn)] = f2tf(pb1.w);
            } else {
                uint4 u0 = make_uint4(f2tf(pb0.x), f2tf(pb0.y), f2tf(pb0.z), f2tf(pb0.w));
                uint4 u1 = make_uint4(f2tf(pb1.x), f2tf(pb1.y), f2tf(pb1.z), f2tf(pb1.w));
                *(uint4*)&Bs1[nxt][bk][swz(bk, bn)]     = u0;
                *(uint4*)&Bs1[nxt][bk][swz(bk, bn + 4)] = u1;
            }
            __syncthreads();
        }
    }

    const float gm = (MODE == 1) ? gamma[0] : 0.0f;
    const float* Rp = (MODE == 1) ? res + (size_t)b * M * N : nullptr;
#pragma unroll
    for (int mi = 0; mi < 4; mi++) {
#pragma unroll
        for (int ni = 0; ni < 4; ni++) {
            const int row = m0 + wm + mi * 16 + g;
            const int col = n0 + wn + ni * 8 + 2 * tq;
            const float* a = acc[mi][ni];
            float2 v0, v1;
            if (MODE == 1) {
                float2 r0 = *(const float2*)&Rp[(size_t)row * N + col];
                float2 r1 = *(const float2*)&Rp[(size_t)(row + 8) * N + col];
                v0.x = fmaf(gm, a[0], r0.x); v0.y = fmaf(gm, a[1], r0.y);
                v1.x = fmaf(gm, a[2], r1.x); v1.y = fmaf(gm, a[3], r1.y);
            } else {
                v0.x = a[0] * scale; v0.y = a[1] * scale;
                v1.x = a[2] * scale; v1.y = a[3] * scale;
            }
            *(float2*)&Cp[(size_t)row * N + col]       = v0;
            *(float2*)&Cp[(size_t)(row + 8) * N + col] = v1;
        }
    }
}

// ---------------------------------------------------------------------------
// Softmax over last dim (512). One block (128 threads) per row, 4 elems/thread.
// ---------------------------------------------------------------------------
__global__ __launch_bounds__(128)
void softmax512_kernel(float* __restrict__ data)
{
    __shared__ float red[4];
    float* p = data + (size_t)blockIdx.x * 512;
    const int t    = threadIdx.x;
    const int lane = t & 31;
    const int warp = t >> 5;

    float4 v = *(const float4*)&p[t << 2];

    float m = fmaxf(fmaxf(v.x, v.y), fmaxf(v.z, v.w));
#pragma unroll
    for (int o = 16; o > 0; o >>= 1)
        m = fmaxf(m, __shfl_xor_sync(0xffffffffu, m, o));
    if (lane == 0) red[warp] = m;
    __syncthreads();
    m = fmaxf(fmaxf(red[0], red[1]), fmaxf(red[2], red[3]));

    v.x = expf(v.x - m); v.y = expf(v.y - m);
    v.z = expf(v.z - m); v.w = expf(v.w - m);

    float s = v.x + v.y + v.z + v.w;
#pragma unroll
    for (int o = 16; o > 0; o >>= 1)
        s += __shfl_xor_sync(0xffffffffu, s, o);
    __syncthreads();
    if (lane == 0) red[warp] = s;
    __syncthreads();
    s = red[0] + red[1] + red[2] + red[3];

    const float inv = 1.0f / s;
    v.x *= inv; v.y *= inv; v.z *= inv; v.w *= inv;
    *(float4*)&p[t << 2] = v;
}

// ---------------------------------------------------------------------------
extern "C" void kernel_launch(void* const* d_in, const int* in_sizes, int n_in,
                              void* d_out, int out_size)
{
    const float* x      = (const float*)d_in[0];   // (16,512,64,64)
    const float* conv_w = (const float*)d_in[1];   // (256,512,1,1)
    const float* conv_b = (const float*)d_in[2];   // (256,)
    const float* gamma  = (const float*)d_in[3];   // (1,)
    float*       out    = (float*)d_out;           // (16,256,64,64)

    float* q    = nullptr;
    float* attn = nullptr;
    uint2* wsp  = nullptr;
    cudaGetSymbolAddress((void**)&q,    g_q);
    cudaGetSymbolAddress((void**)&attn, g_attn);
    cudaGetSymbolAddress((void**)&wsp,  g_wsplit);

    // Pre-split W (256*512 = 131072 elements)
    presplit_w_kernel<<<512, 256>>>(conv_w, wsp);

    // GEMM1: q = W @ x + bias   (M=256, N=4096, K=512)  3xTF32, 2048 CTAs
    {
        dim3 grid(NHW / 64, NC1 / 128, NB);
        gemm1_3x_kernel<<<grid, 256>>>(wsp, x, conv_b, q, NC1, NHW, NC);
    }
    // GEMM2: energy = q @ x^T / 64  (M=256, N=512, K=4096)  1xTF32, 128 CTAs
    {
        dim3 grid(NC / 128, NC1 / 128, NB);
        mma_gemm1x_kernel<2><<<grid, 256>>>(q, x, nullptr, nullptr, attn,
                                            NC1, NC, NHW, 1.0f / 64.0f);
    }
    // softmax over C (512), in place
    softmax512_kernel<<<NB * NC1, 128>>>(attn);

    // GEMM3: out = gamma*(attn @ x) + q  (M=256, N=4096, K=512)  1xTF32, 1024 CTAs
    {
        dim3 grid(NHW / 128, NC1 / 128, NB);
        mma_gemm1x_kernel<1><<<grid, 256>>>(attn, x, gamma, q, out,
                                            NC1, NHW, NC, 1.0f);
    }
}

// round 17
// speedup vs baseline: 1.5349x; 1.0341x over previous
#include <cuda_runtime.h>

// CAM_Module channel attention. B=16, C=512, C1=256, HW=4096
//   q      = W[256,512] @ x_b[512,4096] + bias            (GEMM1, NN, 3xTF32)
//   energy = q[256,4096] @ x_b[512,4096]^T / 64           (GEMM2, NT, 1xTF32, split-K x4)
//   attn   = softmax(energy, last dim 512)                (sums 4 K-slices)
//   out    = gamma * (attn[256,512] @ x_b[512,4096]) + q  (GEMM3, NN, 1xTF32)

static constexpr int NB  = 16;
static constexpr int NC  = 512;
static constexpr int NC1 = 256;
static constexpr int NHW = 4096;
static constexpr int KS  = 4;                            // GEMM2 K-slices
static constexpr size_t EPLANE = (size_t)NB * NC1 * NC;  // partial-energy plane

__device__ float g_q[(size_t)NB * NC1 * NHW];    // 64 MB scratch
__device__ float g_epart[KS * EPLANE];           // 32 MB partial energies
__device__ float g_attn[EPLANE];                 //  8 MB attention
__device__ uint2 g_wsplit[NC1 * NC];             //  1 MB pre-split conv_w

__device__ __forceinline__ unsigned f2tf(float f) {
    unsigned u;
    asm("cvt.rna.tf32.f32 %0, %1;" : "=r"(u) : "f"(f));
    return u;
}

__device__ __forceinline__ uint2 split_tf32(float v) {
    const unsigned hi = f2tf(v);
    const unsigned lo = f2tf(v - __uint_as_float(hi));
    return make_uint2(hi, lo);
}

// XOR swizzle on the m index (verified R7/R10/R12).
__device__ __forceinline__ int swz(int k, int m) {
    return m ^ ((((k & 3) ^ (k >> 2))) << 2);
}

__device__ __forceinline__ void mma_tf32(float* c, const unsigned* a, const unsigned* b) {
    asm volatile(
        "mma.sync.aligned.m16n8k8.row.col.f32.tf32.tf32.f32 "
        "{%0,%1,%2,%3}, {%4,%5,%6,%7}, {%8,%9}, {%0,%1,%2,%3};"
        : "+f"(c[0]), "+f"(c[1]), "+f"(c[2]), "+f"(c[3])
        : "r"(a[0]), "r"(a[1]), "r"(a[2]), "r"(a[3]),
          "r"(b[0]), "r"(b[1]));
}

// ---------------------------------------------------------------------------
__global__ void presplit_w_kernel(const float* __restrict__ w, uint2* __restrict__ o)
{
    const int i = blockIdx.x * blockDim.x + threadIdx.x;
    o[i] = split_tf32(w[i]);
}

// ---------------------------------------------------------------------------
// GEMM1 (3xTF32): q = W @ x + bias. BM=128 x BN=128 x BK=8, 256 threads,
// 8 warps (2 M x 4 N), warp tile 64x32 = 4x4 m16n8k8 (x3 split terms).
// A = pre-split W (uint2). grid (NHW/128, NC1/128, NB)
// ---------------------------------------------------------------------------
__global__ __launch_bounds__(256, 2)
void gemm1_3x_kernel(const uint2* __restrict__ Wsp, const float* __restrict__ x,
                     const float* __restrict__ bias, float* __restrict__ Cout,
                     int M, int N, int K)
{
    const int b = blockIdx.z;
    const float* B = x + (size_t)b * K * N;
    float*      Cp = Cout + (size_t)b * M * N;

    __shared__ __align__(16) uint2 As2[2][8][128];   // 16 KB
    __shared__ __align__(16) uint2 Bs2[2][8][128];   // 16 KB

    const int t    = threadIdx.x;
    const int lane = t & 31;
    const int warp = t >> 5;
    const int wm   = (warp & 1) * 64;   // 2 m-groups of 64
    const int wn   = (warp >> 1) * 32;  // 4 n-groups of 32
    const int g    = lane >> 2;
    const int tq   = lane & 3;

    const int m0 = blockIdx.y * 128;
    const int n0 = blockIdx.x * 128;

    // A loader: 128 rows x 8 k uint2; thread -> row am, k = ak..ak+3
    const int am = t >> 1;              // 0..127
    const int ak = (t & 1) << 2;        // 0 or 4
    // B loader (NN): 8 rows x 128 n floats; thread -> row bk, 4 n
    const int bk = t >> 5;              // 0..7
    const int bn = (t & 31) << 2;       // 0..124

    float acc[4][4][4];
#pragma unroll
    for (int mi = 0; mi < 4; mi++)
#pragma unroll
        for (int ni = 0; ni < 4; ni++)
#pragma unroll
            for (int r = 0; r < 4; r++) acc[mi][ni][r] = 0.0f;

    const int nT = K >> 3;              // 64 tiles of BK=8

    const uint4* W4 = (const uint4*)Wsp;
    uint4 wa0 = W4[((size_t)(m0 + am) * K + ak) >> 1];
    uint4 wa1 = W4[(((size_t)(m0 + am) * K + ak) >> 1) + 1];
    float4 pb = *(const float4*)&B[(size_t)bk * N + n0 + bn];

    {
        As2[0][ak + 0][swz(ak + 0, am)] = make_uint2(wa0.x, wa0.y);
        As2[0][ak + 1][swz(ak + 1, am)] = make_uint2(wa0.z, wa0.w);
        As2[0][ak + 2][swz(ak + 2, am)] = make_uint2(wa1.x, wa1.y);
        As2[0][ak + 3][swz(ak + 3, am)] = make_uint2(wa1.z, wa1.w);
        Bs2[0][bk][swz(bk, bn + 0)] = split_tf32(pb.x);
        Bs2[0][bk][swz(bk, bn + 1)] = split_tf32(pb.y);
        Bs2[0][bk][swz(bk, bn + 2)] = split_tf32(pb.z);
        Bs2[0][bk][swz(bk, bn + 3)] = split_tf32(pb.w);
    }
    __syncthreads();

    for (int kt = 0; kt < nT; kt++) {
        const int  cur      = kt & 1;
        const bool has_next = (kt + 1 < nT);
        if (has_next) {
            const int k0 = (kt + 1) << 3;
            wa0 = W4[((size_t)(m0 + am) * K + k0 + ak) >> 1];
            wa1 = W4[(((size_t)(m0 + am) * K + k0 + ak) >> 1) + 1];
            pb  = *(const float4*)&B[(size_t)(k0 + bk) * N + n0 + bn];
        }

        {
            uint2 bf[4][2];
            const int k0r = tq;
            const int k1r = tq + 4;
#pragma unroll
            for (int ni = 0; ni < 4; ni++) {
                const int c = wn + ni * 8 + g;
                bf[ni][0] = Bs2[cur][k0r][swz(k0r, c)];
                bf[ni][1] = Bs2[cur][k1r][swz(k1r, c)];
            }
#pragma unroll
            for (int mi = 0; mi < 4; mi++) {
                const int r = wm + mi * 16 + g;
                uint2 a0 = As2[cur][k0r][swz(k0r, r)];
                uint2 a1 = As2[cur][k0r][swz(k0r, r + 8)];
                uint2 a2 = As2[cur][k1r][swz(k1r, r)];
                uint2 a3 = As2[cur][k1r][swz(k1r, r + 8)];
                const unsigned ah[4] = {a0.x, a1.x, a2.x, a3.x};
                const unsigned al[4] = {a0.y, a1.y, a2.y, a3.y};
#pragma unroll
                for (int ni = 0; ni < 4; ni++) {
                    const unsigned bh[2] = {bf[ni][0].x, bf[ni][1].x};
                    const unsigned bl[2] = {bf[ni][0].y, bf[ni][1].y};
                    mma_tf32(acc[mi][ni], ah, bl);
                    mma_tf32(acc[mi][ni], al, bh);
                    mma_tf32(acc[mi][ni], ah, bh);
                }
            }
        }

        if (has_next) {
            const int nxt = cur ^ 1;
            As2[nxt][ak + 0][swz(ak + 0, am)] = make_uint2(wa0.x, wa0.y);
            As2[nxt][ak + 1][swz(ak + 1, am)] = make_uint2(wa0.z, wa0.w);
            As2[nxt][ak + 2][swz(ak + 2, am)] = make_uint2(wa1.x, wa1.y);
            As2[nxt][ak + 3][swz(ak + 3, am)] = make_uint2(wa1.z, wa1.w);
            Bs2[nxt][bk][swz(bk, bn + 0)] = split_tf32(pb.x);
            Bs2[nxt][bk][swz(bk, bn + 1)] = split_tf32(pb.y);
            Bs2[nxt][bk][swz(bk, bn + 2)] = split_tf32(pb.z);
            Bs2[nxt][bk][swz(bk, bn + 3)] = split_tf32(pb.w);
            __syncthreads();
        }
    }

#pragma unroll
    for (int mi = 0; mi < 4; mi++) {
#pragma unroll
        for (int ni = 0; ni < 4; ni++) {
            const int row = m0 + wm + mi * 16 + g;
            const int col = n0 + wn + ni * 8 + 2 * tq;
            const float* a = acc[mi][ni];
            const float b0 = bias[row], b1 = bias[row + 8];
            float2 v0 = make_float2(a[0] + b0, a[1] + b0);
            float2 v1 = make_float2(a[2] + b1, a[3] + b1);
            *(float2*)&Cp[(size_t)row * N + col]       = v0;
            *(float2*)&Cp[(size_t)(row + 8) * N + col] = v1;
        }
    }
}

// ---------------------------------------------------------------------------
// 1xTF32 GEMM: BM=128 x BN=128 x BK=16, 256 threads, 64x32 warp tiles.
// MODE 1: NN, A per-batch (attn), C = gamma*(A@B) + res; lda=K; grid (N/128, M/128, NB)
// MODE 2: NT split-K: A=q (lda), B=x [N,lda]; slice s = blockIdx.x>>2;
//         C = scale*(A@B^T) partial -> epart plane s.  grid (4*KS, M/128, NB)
// ---------------------------------------------------------------------------
template <int MODE>
__global__ __launch_bounds__(256, 2)
void mma_gemm1x_kernel(const float* __restrict__ A_, const float* __restrict__ x,
                       const float* __restrict__ gamma, const float* __restrict__ res,
                       float* __restrict__ Cout, int M, int N, int K, int lda,
                       float scale)
{
    const int b = blockIdx.z;
    int bx = blockIdx.x, s = 0;
    if (MODE == 2) { s = bx >> 2; bx &= 3; }

    const float* A = A_ + (size_t)b * M * lda;
    const float* B = (MODE == 2) ? x + (size_t)b * N * lda : x + (size_t)b * K * N;
    if (MODE == 2) { A += (size_t)s * K; B += (size_t)s * K; }
    float* Cp = (MODE == 2)
        ? Cout + (size_t)s * EPLANE + (size_t)b * M * N
        : Cout + (size_t)b * M * N;

    __shared__ __align__(16) unsigned As1[2][16][128];  // 16 KB
    __shared__ __align__(16) unsigned Bs1[2][16][128];  // 16 KB

    const int t    = threadIdx.x;
    const int lane = t & 31;
    const int warp = t >> 5;
    const int wm   = (warp & 1) * 64;
    const int wn   = (warp >> 1) * 32;
    const int g    = lane >> 2;
    const int tq   = lane & 3;

    const int m0 = blockIdx.y * 128;
    const int n0 = bx * 128;

    const int am = t >> 1;              // 0..127
    const int ak = (t & 1) << 3;        // 0 or 8
    const int bk = t >> 4;              // 0..15
    const int bn = (t & 15) << 3;       // 0..120
    const int cn = t >> 1;              // 0..127
    const int ck = (t & 1) << 3;        // 0 or 8

    float acc[4][4][4];
#pragma unroll
    for (int mi = 0; mi < 4; mi++)
#pragma unroll
        for (int ni = 0; ni < 4; ni++)
#pragma unroll
            for (int r = 0; r < 4; r++) acc[mi][ni][r] = 0.0f;

    const int nT = K >> 4;

    float4 pa0 = *(const float4*)&A[(size_t)(m0 + am) * lda + ak];
    float4 pa1 = *(const float4*)&A[(size_t)(m0 + am) * lda + ak + 4];
    float4 pb0, pb1;
    if (MODE == 2) {
        pb0 = *(const float4*)&B[(size_t)(n0 + cn) * lda + ck];
        pb1 = *(const float4*)&B[(size_t)(n0 + cn) * lda + ck + 4];
    } else {
        pb0 = *(const float4*)&B[(size_t)bk * N + n0 + bn];
        pb1 = *(const float4*)&B[(size_t)bk * N + n0 + bn + 4];
    }

    {
        As1[0][ak + 0][swz(ak + 0, am)] = f2tf(pa0.x);
        As1[0][ak + 1][swz(ak + 1, am)] = f2tf(pa0.y);
        As1[0][ak + 2][swz(ak + 2, am)] = f2tf(pa0.z);
        As1[0][ak + 3][swz(ak + 3, am)] = f2tf(pa0.w);
        As1[0][ak + 4][swz(ak + 4, am)] = f2tf(pa1.x);
        As1[0][ak + 5][swz(ak + 5, am)] = f2tf(pa1.y);
        As1[0][ak + 6][swz(ak + 6, am)] = f2tf(pa1.z);
        As1[0][ak + 7][swz(ak + 7, am)] = f2tf(pa1.w);
        if (MODE == 2) {
            Bs1[0][ck + 0][swz(ck + 0, cn)] = f2tf(pb0.x);
            Bs1[0][ck + 1][swz(ck + 1, cn)] = f2tf(pb0.y);
            Bs1[0][ck + 2][swz(ck + 2, cn)] = f2tf(pb0.z);
            Bs1[0][ck + 3][swz(ck + 3, cn)] = f2tf(pb0.w);
            Bs1[0][ck + 4][swz(ck + 4, cn)] = f2tf(pb1.x);
            Bs1[0][ck + 5][swz(ck + 5, cn)] = f2tf(pb1.y);
            Bs1[0][ck + 6][swz(ck + 6, cn)] = f2tf(pb1.z);
            Bs1[0][ck + 7][swz(ck + 7, cn)] = f2tf(pb1.w);
        } else {
            uint4 u0 = make_uint4(f2tf(pb0.x), f2tf(pb0.y), f2tf(pb0.z), f2tf(pb0.w));
            uint4 u1 = make_uint4(f2tf(pb1.x), f2tf(pb1.y), f2tf(pb1.z), f2tf(pb1.w));
            *(uint4*)&Bs1[0][bk][swz(bk, bn)]     = u0;
            *(uint4*)&Bs1[0][bk][swz(bk, bn + 4)] = u1;
        }
    }
    __syncthreads();

    for (int kt = 0; kt < nT; kt++) {
        const int  cur      = kt & 1;
        const bool has_next = (kt + 1 < nT);
        if (has_next) {
            const int k0 = (kt + 1) << 4;
            pa0 = *(const float4*)&A[(size_t)(m0 + am) * lda + k0 + ak];
            pa1 = *(const float4*)&A[(size_t)(m0 + am) * lda + k0 + ak + 4];
            if (MODE == 2) {
                pb0 = *(const float4*)&B[(size_t)(n0 + cn) * lda + k0 + ck];
                pb1 = *(const float4*)&B[(size_t)(n0 + cn) * lda + k0 + ck + 4];
            } else {
                pb0 = *(const float4*)&B[(size_t)(k0 + bk) * N + n0 + bn];
                pb1 = *(const float4*)&B[(size_t)(k0 + bk) * N + n0 + bn + 4];
            }
        }

#pragma unroll
        for (int ks = 0; ks < 16; ks += 8) {
            unsigned bf[4][2];
            const int k0r = ks + tq;
            const int k1r = ks + tq + 4;
#pragma unroll
            for (int ni = 0; ni < 4; ni++) {
                const int c = wn + ni * 8 + g;
                bf[ni][0] = Bs1[cur][k0r][swz(k0r, c)];
                bf[ni][1] = Bs1[cur][k1r][swz(k1r, c)];
            }
#pragma unroll
            for (int mi = 0; mi < 4; mi++) {
                const int r = wm + mi * 16 + g;
                unsigned a[4];
                a[0] = As1[cur][k0r][swz(k0r, r)];
                a[1] = As1[cur][k0r][swz(k0r, r + 8)];
                a[2] = As1[cur][k1r][swz(k1r, r)];
                a[3] = As1[cur][k1r][swz(k1r, r + 8)];
#pragma unroll
                for (int ni = 0; ni < 4; ni++)
                    mma_tf32(acc[mi][ni], a, bf[ni]);
            }
        }

        if (has_next) {
            const int nxt = cur ^ 1;
            As1[nxt][ak + 0][swz(ak + 0, am)] = f2tf(pa0.x);
            As1[nxt][ak + 1][swz(ak + 1, am)] = f2tf(pa0.y);
            As1[nxt][ak + 2][swz(ak + 2, am)] = f2tf(pa0.z);
            As1[nxt][ak + 3][swz(ak + 3, am)] = f2tf(pa0.w);
            As1[nxt][ak + 4][swz(ak + 4, am)] = f2tf(pa1.x);
            As1[nxt][ak + 5][swz(ak + 5, am)] = f2tf(pa1.y);
            As1[nxt][ak + 6][swz(ak + 6, am)] = f2tf(pa1.z);
            As1[nxt][ak + 7][swz(ak + 7, am)] = f2tf(pa1.w);
            if (MODE == 2) {
                Bs1[nxt][ck + 0][swz(ck + 0, cn)] = f2tf(pb0.x);
                Bs1[nxt][ck + 1][swz(ck + 1, cn)] = f2tf(pb0.y);
                Bs1[nxt][ck + 2][swz(ck + 2, cn)] = f2tf(pb0.z);
                Bs1[nxt][ck + 3][swz(ck + 3, cn)] = f2tf(pb0.w);
                Bs1[nxt][ck + 4][swz(ck + 4, cn)] = f2tf(pb1.x);
                Bs1[nxt][ck + 5][swz(ck + 5, cn)] = f2tf(pb1.y);
                Bs1[nxt][ck + 6][swz(ck + 6, cn)] = f2tf(pb1.z);
                Bs1[nxt][ck + 7][swz(ck + 7, cn)] = f2tf(pb1.w);
            } else {
                uint4 u0 = make_uint4(f2tf(pb0.x), f2tf(pb0.y), f2tf(pb0.z), f2tf(pb0.w));
                uint4 u1 = make_uint4(f2tf(pb1.x), f2tf(pb1.y), f2tf(pb1.z), f2tf(pb1.w));
                *(uint4*)&Bs1[nxt][bk][swz(bk, bn)]     = u0;
                *(uint4*)&Bs1[nxt][bk][swz(bk, bn + 4)] = u1;
            }
            __syncthreads();
        }
    }

    const float gm = (MODE == 1) ? gamma[0] : 0.0f;
    const float* Rp = (MODE == 1) ? res + (size_t)b * M * N : nullptr;
#pragma unroll
    for (int mi = 0; mi < 4; mi++) {
#pragma unroll
        for (int ni = 0; ni < 4; ni++) {
            const int row = m0 + wm + mi * 16 + g;
            const int col = n0 + wn + ni * 8 + 2 * tq;
            const float* a = acc[mi][ni];
            float2 v0, v1;
            if (MODE == 1) {
                float2 r0 = *(const float2*)&Rp[(size_t)row * N + col];
                float2 r1 = *(const float2*)&Rp[(size_t)(row + 8) * N + col];
                v0.x = fmaf(gm, a[0], r0.x); v0.y = fmaf(gm, a[1], r0.y);
                v1.x = fmaf(gm, a[2], r1.x); v1.y = fmaf(gm, a[3], r1.y);
            } else {
                v0.x = a[0] * scale; v0.y = a[1] * scale;
                v1.x = a[2] * scale; v1.y = a[3] * scale;
            }
            *(float2*)&Cp[(size_t)row * N + col]       = v0;
            *(float2*)&Cp[(size_t)(row + 8) * N + col] = v1;
        }
    }
}

// ---------------------------------------------------------------------------
// Softmax over 512 with 4-way split-K reduction. One block per row.
// ---------------------------------------------------------------------------
__global__ __launch_bounds__(128)
void softmax512_sum_kernel(const float* __restrict__ ep, float* __restrict__ attn)
{
    __shared__ float red[4];
    const size_t row = blockIdx.x;
    const int t    = threadIdx.x;
    const int lane = t & 31;
    const int warp = t >> 5;
    const size_t off = row * 512 + (t << 2);

    float4 v  = *(const float4*)&ep[off];
    float4 v1 = *(const float4*)&ep[EPLANE + off];
    float4 v2 = *(const float4*)&ep[2 * EPLANE + off];
    float4 v3 = *(const float4*)&ep[3 * EPLANE + off];
    v.x += v1.x + v2.x + v3.x;
    v.y += v1.y + v2.y + v3.y;
    v.z += v1.z + v2.z + v3.z;
    v.w += v1.w + v2.w + v3.w;

    float m = fmaxf(fmaxf(v.x, v.y), fmaxf(v.z, v.w));
#pragma unroll
    for (int o = 16; o > 0; o >>= 1)
        m = fmaxf(m, __shfl_xor_sync(0xffffffffu, m, o));
    if (lane == 0) red[warp] = m;
    __syncthreads();
    m = fmaxf(fmaxf(red[0], red[1]), fmaxf(red[2], red[3]));

    v.x = expf(v.x - m); v.y = expf(v.y - m);
    v.z = expf(v.z - m); v.w = expf(v.w - m);

    float s = v.x + v.y + v.z + v.w;
#pragma unroll
    for (int o = 16; o > 0; o >>= 1)
        s += __shfl_xor_sync(0xffffffffu, s, o);
    __syncthreads();
    if (lane == 0) red[warp] = s;
    __syncthreads();
    s = red[0] + red[1] + red[2] + red[3];

    const float inv = 1.0f / s;
    v.x *= inv; v.y *= inv; v.z *= inv; v.w *= inv;
    *(float4*)&attn[row * 512 + (t << 2)] = v;
}

// ---------------------------------------------------------------------------
extern "C" void kernel_launch(void* const* d_in, const int* in_sizes, int n_in,
                              void* d_out, int out_size)
{
    const float* x      = (const float*)d_in[0];   // (16,512,64,64)
    const float* conv_w = (const float*)d_in[1];   // (256,512,1,1)
    const float* conv_b = (const float*)d_in[2];   // (256,)
    const float* gamma  = (const float*)d_in[3];   // (1,)
    float*       out    = (float*)d_out;           // (16,256,64,64)

    float* q    = nullptr;
    float* ep   = nullptr;
    float* attn = nullptr;
    uint2* wsp  = nullptr;
    cudaGetSymbolAddress((void**)&q,    g_q);
    cudaGetSymbolAddress((void**)&ep,   g_epart);
    cudaGetSymbolAddress((void**)&attn, g_attn);
    cudaGetSymbolAddress((void**)&wsp,  g_wsplit);

    // Pre-split W
    presplit_w_kernel<<<512, 256>>>(conv_w, wsp);

    // GEMM1: q = W @ x + bias   (M=256, N=4096, K=512)  3xTF32, 1024 CTAs
    {
        dim3 grid(NHW / 128, NC1 / 128, NB);
        gemm1_3x_kernel<<<grid, 256>>>(wsp, x, conv_b, q, NC1, NHW, NC);
    }
    // GEMM2: energy partials = q @ x^T / 64, split-K x4 -> 512 CTAs
    {
        dim3 grid((NC / 128) * KS, NC1 / 128, NB);
        mma_gemm1x_kernel<2><<<grid, 256>>>(q, x, nullptr, nullptr, ep,
                                            NC1, NC, NHW / KS, NHW, 1.0f / 64.0f);
    }
    // softmax over C (512) with 4-plane reduction
    softmax512_sum_kernel<<<NB * NC1, 128>>>(ep, attn);

    // GEMM3: out = gamma*(attn @ x) + q  (M=256, N=4096, K=512)  1xTF32, 1024 CTAs
    {
        dim3 grid(NHW / 128, NC1 / 128, NB);
        mma_gemm1x_kernel<1><<<grid, 256>>>(attn, x, gamma, q, out,
                                            NC1, NHW, NC, NC, 1.0f);
    }
}